// round 8
// baseline (speedup 1.0000x reference)
#include <cuda_runtime.h>
#include <cstdint>

// EmbeddingWithDropout:
//   out[t, :] = weight[x[t], :] * ((u[x[t]] >= 0.1f) ? (1.0f/0.9f) : 0.0f)
// x: int32 [131072], weight: f32 [100000,128], u: f32 [100000], out: f32 [131072,128]
//
// One warp handles 8 tokens; each lane owns one float4 of the 128-wide row
// (32 x 16 B = 512 B, coalesced gather + store). Two batched memory waves
// (indices, then u+weight gathers) for MLP=16 on the expensive wave.
//
// Round-7 change: output stores use st.global.wt (__stwt, write-through).
// Evidence from R3-R6: time pinned at ~17us regardless of MLP/instruction
// count/evict hints => queueing on a ~2.8TB/s mixed read+writeback DRAM path
// caused by the 67MB output stream thrashing the 51MB weight table out of L2
// (118MB demand vs 126MB capacity). Write-through stores keep output OUT of
// L2 entirely: the table becomes fully L2-resident across graph replays
// (gather misses -> ~0) and DRAM sees only a clean streaming write pattern.

#define TOK_PER_WARP 8

__global__ void __launch_bounds__(256, 4)
embedding_dropout_kernel(const int* __restrict__ x,
                         const float4* __restrict__ weight,   // [vocab*32] float4
                         const float* __restrict__ u,         // [vocab]
                         float4* __restrict__ out,            // [n_tok*32] float4
                         int n_tok)
{
    const int gtid = blockIdx.x * blockDim.x + threadIdx.x;
    const int warp = gtid >> 5;
    const int lane = threadIdx.x & 31;
    const int base = warp * TOK_PER_WARP;
    if (base >= n_tok) return;

    if (base + TOK_PER_WARP <= n_tok) {
        // ---- Wave 1: 8 independent index loads (uniform broadcast) ----
        int rows[TOK_PER_WARP];
        #pragma unroll
        for (int i = 0; i < TOK_PER_WARP; i++)
            rows[i] = __ldg(&x[base + i]);

        // ---- Wave 2: 8 u-loads + 8 row-gathers, all independent ----
        float uv[TOK_PER_WARP];
        float4 v[TOK_PER_WARP];
        #pragma unroll
        for (int i = 0; i < TOK_PER_WARP; i++) {
            uv[i] = __ldg(&u[rows[i]]);
            v[i]  = __ldg(&weight[(size_t)rows[i] * 32 + lane]);
        }

        // ---- Scale + WRITE-THROUGH store (output never occupies L2) ----
        #pragma unroll
        for (int i = 0; i < TOK_PER_WARP; i++) {
            const float keep = (uv[i] >= 0.1f) ? (1.0f / 0.9f) : 0.0f;
            v[i].x *= keep;
            v[i].y *= keep;
            v[i].z *= keep;
            v[i].w *= keep;
            __stwt(&out[(size_t)(base + i) * 32 + lane], v[i]);
        }
    } else {
        // ---- Tail path ----
        for (int i = 0; base + i < n_tok; i++) {
            const int row = __ldg(&x[base + i]);
            const float keep = (__ldg(&u[row]) >= 0.1f) ? (1.0f / 0.9f) : 0.0f;
            float4 v = __ldg(&weight[(size_t)row * 32 + lane]);
            v.x *= keep; v.y *= keep; v.z *= keep; v.w *= keep;
            __stwt(&out[(size_t)(base + i) * 32 + lane], v);
        }
    }
}

extern "C" void kernel_launch(void* const* d_in, const int* in_sizes, int n_in,
                              void* d_out, int out_size)
{
    const int*    x      = (const int*)d_in[0];
    const float4* weight = (const float4*)d_in[1];
    const float*  u      = (const float*)d_in[2];
    float4*       out    = (float4*)d_out;

    const int n_tok = in_sizes[0];                            // 131072
    const int threads = 256;                                  // 8 warps/block
    const int tok_per_block = (threads / 32) * TOK_PER_WARP;  // 64
    const int blocks = (n_tok + tok_per_block - 1) / tok_per_block;

    embedding_dropout_kernel<<<blocks, threads>>>(x, weight, u, out, n_tok);
}

// round 9
// speedup vs baseline: 1.0321x; 1.0321x over previous
#include <cuda_runtime.h>
#include <cstdint>

// EmbeddingWithDropout:
//   out[t, :] = weight[x[t], :] * ((u[x[t]] >= 0.1f) ? (1.0f/0.9f) : 0.0f)
// x: int32 [131072], weight: f32 [100000,128], u: f32 [100000], out: f32 [131072,128]
//
// One warp handles 8 tokens; each lane owns one float4 of the 128-wide row
// (32 x 16 B = 512 B, coalesced gather + store).
//
// Round-8 model (from R3-R7 evidence): time == scattered-DRAM-read traffic /
// ~2.8TB/s. Output stays dirty-resident in L2 (overwritten every graph replay,
// no writeback); DRAM traffic is the ~73K distinct 512B row reads that miss L2
// due to set-conflict churn. The only lever left is read-traffic reduction:
// ~10% of rows have keep==0 (dropout), so their row gather is skipped entirely
// via predicated loads (predicated-off LDG issues no memory transaction).

#define TOK_PER_WARP 8

__global__ void __launch_bounds__(256, 4)
embedding_dropout_kernel(const int* __restrict__ x,
                         const float4* __restrict__ weight,   // [vocab*32] float4
                         const float* __restrict__ u,         // [vocab]
                         float4* __restrict__ out,            // [n_tok*32] float4
                         int n_tok)
{
    const int gtid = blockIdx.x * blockDim.x + threadIdx.x;
    const int warp = gtid >> 5;
    const int lane = threadIdx.x & 31;
    const int base = warp * TOK_PER_WARP;
    if (base >= n_tok) return;

    if (base + TOK_PER_WARP <= n_tok) {
        // ---- Wave 1: 8 independent index loads (uniform broadcast) ----
        int rows[TOK_PER_WARP];
        #pragma unroll
        for (int i = 0; i < TOK_PER_WARP; i++)
            rows[i] = __ldg(&x[base + i]);

        // ---- Wave 2: 8 u-loads (tiny, L2-resident) ----
        float uv[TOK_PER_WARP];
        #pragma unroll
        for (int i = 0; i < TOK_PER_WARP; i++)
            uv[i] = __ldg(&u[rows[i]]);

        // ---- Wave 3: predicated row gathers — dropped rows read NOTHING ----
        float4 v[TOK_PER_WARP];
        #pragma unroll
        for (int i = 0; i < TOK_PER_WARP; i++) {
            v[i] = make_float4(0.f, 0.f, 0.f, 0.f);
            if (uv[i] >= 0.1f)   // warp-uniform condition, predicated LDG
                v[i] = __ldg(&weight[(size_t)rows[i] * 32 + lane]);
        }

        // ---- Scale + store (default caching: output lives in L2) ----
        #pragma unroll
        for (int i = 0; i < TOK_PER_WARP; i++) {
            v[i].x *= (1.0f / 0.9f);
            v[i].y *= (1.0f / 0.9f);
            v[i].z *= (1.0f / 0.9f);
            v[i].w *= (1.0f / 0.9f);
            out[(size_t)(base + i) * 32 + lane] = v[i];
        }
    } else {
        // ---- Tail path ----
        for (int i = 0; base + i < n_tok; i++) {
            const int row = __ldg(&x[base + i]);
            const float uv = __ldg(&u[row]);
            float4 v = make_float4(0.f, 0.f, 0.f, 0.f);
            if (uv >= 0.1f)
                v = __ldg(&weight[(size_t)row * 32 + lane]);
            v.x *= (1.0f / 0.9f);
            v.y *= (1.0f / 0.9f);
            v.z *= (1.0f / 0.9f);
            v.w *= (1.0f / 0.9f);
            out[(size_t)(base + i) * 32 + lane] = v;
        }
    }
}

extern "C" void kernel_launch(void* const* d_in, const int* in_sizes, int n_in,
                              void* d_out, int out_size)
{
    const int*    x      = (const int*)d_in[0];
    const float4* weight = (const float4*)d_in[1];
    const float*  u      = (const float*)d_in[2];
    float4*       out    = (float4*)d_out;

    const int n_tok = in_sizes[0];                            // 131072
    const int threads = 256;                                  // 8 warps/block
    const int tok_per_block = (threads / 32) * TOK_PER_WARP;  // 64
    const int blocks = (n_tok + tok_per_block - 1) / tok_per_block;

    embedding_dropout_kernel<<<blocks, threads>>>(x, weight, u, out, n_tok);
}